// round 4
// baseline (speedup 1.0000x reference)
#include <cuda_runtime.h>
#include <math.h>

// Problem constants
#define B_ 4
#define S_ 2048
#define DM 1024
#define NH 16
#define DK 64
#define OUT_ELEMS ((size_t)B_ * S_ * DM)            // 8,388,608

// Scratch (no cudaMalloc allowed)
__device__ float g_Q[B_ * NH * S_ * DK];
__device__ float g_K[B_ * NH * S_ * DK];
__device__ float g_V[B_ * NH * S_ * DK];
__device__ float g_ctx[(size_t)B_ * S_ * DM];

__device__ __forceinline__ unsigned f2tf(float x) {
    unsigned u;
    asm("cvt.rna.tf32.f32 %0, %1;" : "=r"(u) : "f"(x));
    return u;
}

__device__ __forceinline__ void mma8(float* c, const unsigned* a, const unsigned* b) {
    asm volatile(
        "mma.sync.aligned.m16n8k8.row.col.f32.tf32.tf32.f32 "
        "{%0,%1,%2,%3}, {%4,%5,%6,%7}, {%8,%9}, {%0,%1,%2,%3};"
        : "+f"(c[0]), "+f"(c[1]), "+f"(c[2]), "+f"(c[3])
        : "r"(a[0]), "r"(a[1]), "r"(a[2]), "r"(a[3]), "r"(b[0]), "r"(b[1]));
}

// ---------------------------------------------------------------------------
// Projection GEMM (tf32 MMA), 512 threads, 128x128x32 tile, warp tile 32x32.
// EPI 0 = head-split store, EPI 1 = plain [M,DM] store.
// ---------------------------------------------------------------------------
template<int EPI>
__global__ void __launch_bounds__(512)
gemm_proj(const float* __restrict__ A, const float* __restrict__ W,
          float* __restrict__ C, const float* __restrict__ bias)
{
    constexpr int BM = 128, BN = 128, BK = 32;
    constexpr int SA = BK + 4, SB = BN + 8;
    __shared__ unsigned As[BM * SA];
    __shared__ unsigned Bs[BK * SB];

    const int tid = threadIdx.x;
    const int lane = tid & 31, wid = tid >> 5;
    const int wm = (wid & 3) * 32, wn = (wid >> 2) * 32;
    const int bm = blockIdx.y * BM, bn = blockIdx.x * BN;

    float acc[2][4][4] = {};
    float4 ra[2], rb[2];

    auto loadA = [&](int k0) {
        #pragma unroll
        for (int i = 0; i < 2; ++i) {
            int f = tid + i * 512;
            int r = f >> 3, c = (f & 7) * 4;
            ra[i] = *reinterpret_cast<const float4*>(A + (size_t)(bm + r) * DM + k0 + c);
        }
    };
    auto loadB = [&](int k0) {
        #pragma unroll
        for (int i = 0; i < 2; ++i) {
            int f = tid + i * 512;
            int r = f >> 5, c = (f & 31) * 4;
            rb[i] = *reinterpret_cast<const float4*>(W + (size_t)(k0 + r) * DM + bn + c);
        }
    };
    auto stage = [&]() {
        #pragma unroll
        for (int i = 0; i < 2; ++i) {
            int f = tid + i * 512;
            int r = f >> 3, c = (f & 7) * 4;
            unsigned* p = &As[r * SA + c];
            p[0] = f2tf(ra[i].x); p[1] = f2tf(ra[i].y); p[2] = f2tf(ra[i].z); p[3] = f2tf(ra[i].w);
            int r2 = f >> 5, c2 = (f & 31) * 4;
            unsigned* q = &Bs[r2 * SB + c2];
            q[0] = f2tf(rb[i].x); q[1] = f2tf(rb[i].y); q[2] = f2tf(rb[i].z); q[3] = f2tf(rb[i].w);
        }
    };

    loadA(0); loadB(0);
    for (int it = 0; it < DM / BK; ++it) {
        if (it) __syncthreads();
        stage();
        __syncthreads();
        if (it + 1 < DM / BK) { loadA((it + 1) * BK); loadB((it + 1) * BK); }

        #pragma unroll
        for (int kk = 0; kk < BK / 8; ++kk) {
            unsigned afr[2][4], bfr[4][2];
            #pragma unroll
            for (int mi = 0; mi < 2; ++mi) {
                int r = wm + mi * 16 + (lane >> 2);
                int c = kk * 8 + (lane & 3);
                afr[mi][0] = As[r * SA + c];
                afr[mi][1] = As[(r + 8) * SA + c];
                afr[mi][2] = As[r * SA + c + 4];
                afr[mi][3] = As[(r + 8) * SA + c + 4];
            }
            #pragma unroll
            for (int ni = 0; ni < 4; ++ni) {
                int n = wn + ni * 8 + (lane >> 2);
                int c = kk * 8 + (lane & 3);
                bfr[ni][0] = Bs[c * SB + n];
                bfr[ni][1] = Bs[(c + 4) * SB + n];
            }
            #pragma unroll
            for (int mi = 0; mi < 2; ++mi)
                #pragma unroll
                for (int ni = 0; ni < 4; ++ni)
                    mma8(acc[mi][ni], afr[mi], bfr[ni]);
        }
    }

    #pragma unroll
    for (int mi = 0; mi < 2; ++mi)
        #pragma unroll
        for (int ni = 0; ni < 4; ++ni)
            #pragma unroll
            for (int e = 0; e < 4; ++e) {
                int m = bm + wm + mi * 16 + (lane >> 2) + ((e >= 2) ? 8 : 0);
                int n = bn + wn + ni * 8 + (lane & 3) * 2 + (e & 1);
                float v = acc[mi][ni][e] + bias[n];
                if (EPI == 0) {
                    int b = m >> 11, s = m & (S_ - 1);
                    int h = n >> 6, d = n & (DK - 1);
                    C[(((size_t)b * NH + h) * S_ + s) * DK + d] = v;
                } else {
                    C[(size_t)m * DM + n] = v;
                }
            }
}

// ---------------------------------------------------------------------------
// Fused attention, 512 threads. Per CTA: 128 q-rows of one (b,h).
// Pass 1: stream K tiles, QK^T MMA, online row max/sum.
// Pass 2: recompute QK^T, p = exp(x-M)/S, write final attn, accumulate P@V.
// V kept [seq][d] in smem; AV B-fragment reads Vs[k*stride + n] (conflict-free).
// ---------------------------------------------------------------------------
#define QS_STRIDE 68
#define PS_STRIDE 132
#define FUSED_SMEM ((3 * 128 * QS_STRIDE + 128 * PS_STRIDE) * 4)   // 172,032 B

__global__ void __launch_bounds__(512, 1)
fused_attn(const float* __restrict__ Q, const float* __restrict__ Km,
           const float* __restrict__ V, float* __restrict__ attn,
           float* __restrict__ ctx)
{
    extern __shared__ unsigned char smem_raw[];
    unsigned* Qs = (unsigned*)smem_raw;                       // [128][68]
    unsigned* Ks = Qs + 128 * QS_STRIDE;                      // [128][68]
    unsigned* Vs = Ks + 128 * QS_STRIDE;                      // [128][68]  (seq-major)
    unsigned* Ps = Vs + 128 * QS_STRIDE;                      // [128][132]
    // reduction scratch overlaps Ps (Ps unused until pass 2)
    float* rowm  = (float*)Ps;          // [128][4]
    float* rowss = rowm + 128 * 4;      // [128][4]
    float* sM    = rowss + 128 * 4;     // [128]
    float* sSinv = sM + 128;            // [128]

    const int tid = threadIdx.x;
    const int lane = tid & 31, wid = tid >> 5;
    const int wm = (wid & 3) * 32;          // warp row (scores & AV)
    const int wn = (wid >> 2) * 32;         // scores warp col
    const int wn2 = (wid >> 2) * 16;        // AV warp col
    const int q0 = blockIdx.x * 128;
    const int bh = blockIdx.y;
    const float scale = 0.125f;

    const float* Qb = Q + (size_t)bh * S_ * DK;
    const float* Kb = Km + (size_t)bh * S_ * DK;
    const float* Vb = V + (size_t)bh * S_ * DK;

    // Load Q tile (128 x 64) as tf32
    #pragma unroll
    for (int i = 0; i < 4; ++i) {
        int f = tid + i * 512;
        int r = f >> 4, c = (f & 15) * 4;
        float4 v = *reinterpret_cast<const float4*>(Qb + (size_t)(q0 + r) * DK + c);
        unsigned* p = &Qs[r * QS_STRIDE + c];
        p[0] = f2tf(v.x); p[1] = f2tf(v.y); p[2] = f2tf(v.z); p[3] = f2tf(v.w);
    }

    float4 rk[4], rv[4];
    auto loadK = [&](int t) {
        #pragma unroll
        for (int i = 0; i < 4; ++i) {
            int f = tid + i * 512;
            int r = f >> 4, c = (f & 15) * 4;
            rk[i] = *reinterpret_cast<const float4*>(Kb + (size_t)(t * 128 + r) * DK + c);
        }
    };
    auto storeK = [&]() {
        #pragma unroll
        for (int i = 0; i < 4; ++i) {
            int f = tid + i * 512;
            int r = f >> 4, c = (f & 15) * 4;
            unsigned* p = &Ks[r * QS_STRIDE + c];
            p[0] = f2tf(rk[i].x); p[1] = f2tf(rk[i].y); p[2] = f2tf(rk[i].z); p[3] = f2tf(rk[i].w);
        }
    };
    auto loadV = [&](int t) {
        #pragma unroll
        for (int i = 0; i < 4; ++i) {
            int f = tid + i * 512;
            int r = f >> 4, c = (f & 15) * 4;
            rv[i] = *reinterpret_cast<const float4*>(Vb + (size_t)(t * 128 + r) * DK + c);
        }
    };
    auto storeV = [&]() {
        #pragma unroll
        for (int i = 0; i < 4; ++i) {
            int f = tid + i * 512;
            int r = f >> 4, c = (f & 15) * 4;
            unsigned* p = &Vs[r * QS_STRIDE + c];
            p[0] = f2tf(rv[i].x); p[1] = f2tf(rv[i].y); p[2] = f2tf(rv[i].z); p[3] = f2tf(rv[i].w);
        }
    };

    // QK^T MMA for the current smem tiles; result in sacc[2][4][4]
    auto qk_mma = [&](float sacc[2][4][4]) {
        #pragma unroll
        for (int kk = 0; kk < 8; ++kk) {
            unsigned afr[2][4], bfr[4][2];
            #pragma unroll
            for (int mi = 0; mi < 2; ++mi) {
                int r = wm + mi * 16 + (lane >> 2);
                int c = kk * 8 + (lane & 3);
                afr[mi][0] = Qs[r * QS_STRIDE + c];
                afr[mi][1] = Qs[(r + 8) * QS_STRIDE + c];
                afr[mi][2] = Qs[r * QS_STRIDE + c + 4];
                afr[mi][3] = Qs[(r + 8) * QS_STRIDE + c + 4];
            }
            #pragma unroll
            for (int ni = 0; ni < 4; ++ni) {
                int n = wn + ni * 8 + (lane >> 2);
                int c = kk * 8 + (lane & 3);
                bfr[ni][0] = Ks[n * QS_STRIDE + c];
                bfr[ni][1] = Ks[n * QS_STRIDE + c + 4];
            }
            #pragma unroll
            for (int mi = 0; mi < 2; ++mi)
                #pragma unroll
                for (int ni = 0; ni < 4; ++ni)
                    mma8(sacc[mi][ni], afr[mi], bfr[ni]);
        }
    };

    float mreg[2][2], sreg[2][2];
    #pragma unroll
    for (int mi = 0; mi < 2; ++mi)
        #pragma unroll
        for (int e = 0; e < 2; ++e) { mreg[mi][e] = -INFINITY; sreg[mi][e] = 0.f; }

    // ---------------- Pass 1: row max + sum ----------------
    loadK(0);
    for (int t = 0; t < S_ / 128; ++t) {
        if (t) __syncthreads();     // previous compute done reading Ks
        storeK();
        __syncthreads();
        if (t + 1 < S_ / 128) loadK(t + 1);

        float sacc[2][4][4] = {};
        qk_mma(sacc);

        #pragma unroll
        for (int mi = 0; mi < 2; ++mi)
            #pragma unroll
            for (int e = 0; e < 2; ++e) {
                float lm = -INFINITY;
                #pragma unroll
                for (int ni = 0; ni < 4; ++ni)
                    lm = fmaxf(lm, fmaxf(sacc[mi][ni][e * 2], sacc[mi][ni][e * 2 + 1]));
                lm *= scale;
                float nm = fmaxf(mreg[mi][e], lm);
                float add = 0.f;
                #pragma unroll
                for (int ni = 0; ni < 4; ++ni) {
                    add += __expf(sacc[mi][ni][e * 2] * scale - nm);
                    add += __expf(sacc[mi][ni][e * 2 + 1] * scale - nm);
                }
                sreg[mi][e] = sreg[mi][e] * __expf(mreg[mi][e] - nm) + add;
                mreg[mi][e] = nm;
            }
    }

    // ---------------- Cross-lane / cross-warp reduction ----------------
    #pragma unroll
    for (int mi = 0; mi < 2; ++mi)
        #pragma unroll
        for (int e = 0; e < 2; ++e) {
            float m = mreg[mi][e], s = sreg[mi][e];
            #pragma unroll
            for (int off = 1; off <= 2; off <<= 1) {
                float om = __shfl_xor_sync(0xFFFFFFFFu, m, off);
                float os = __shfl_xor_sync(0xFFFFFFFFu, s, off);
                float nm = fmaxf(m, om);
                s = s * __expf(m - nm) + os * __expf(om - nm);
                m = nm;
            }
            mreg[mi][e] = m; sreg[mi][e] = s;
        }
    __syncthreads();   // pass-1 Ks readers done; Ps scratch region free
    if ((lane & 3) == 0) {
        int g = wid >> 2;
        #pragma unroll
        for (int mi = 0; mi < 2; ++mi)
            #pragma unroll
            for (int e = 0; e < 2; ++e) {
                int r = wm + mi * 16 + (lane >> 2) + e * 8;
                rowm[r * 4 + g] = mreg[mi][e];
                rowss[r * 4 + g] = sreg[mi][e];
            }
    }
    __syncthreads();
    if (tid < 128) {
        float M = -INFINITY;
        #pragma unroll
        for (int g = 0; g < 4; ++g) M = fmaxf(M, rowm[tid * 4 + g]);
        float S = 0.f;
        #pragma unroll
        for (int g = 0; g < 4; ++g) S += rowss[tid * 4 + g] * __expf(rowm[tid * 4 + g] - M);
        sM[tid] = M;
        sSinv[tid] = 1.0f / S;
    }
    __syncthreads();

    float Mf[2][2], Sf[2][2];
    #pragma unroll
    for (int mi = 0; mi < 2; ++mi)
        #pragma unroll
        for (int e = 0; e < 2; ++e) {
            int r = wm + mi * 16 + (lane >> 2) + e * 8;
            Mf[mi][e] = sM[r];
            Sf[mi][e] = sSinv[r];
        }
    // NOTE: pass-2 Ps writes happen after the first in-loop __syncthreads,
    // which also orders them after every thread's sM/sSinv reads above.

    // ---------------- Pass 2: recompute, write attn, accumulate P@V ------
    float acco[2][2][4] = {};
    float* attn_b = attn + (size_t)bh * S_ * S_;
    const int b = bh >> 4, h = bh & (NH - 1);

    loadK(0); loadV(0);
    for (int t = 0; t < S_ / 128; ++t) {
        if (t) __syncthreads();     // previous AV readers of Vs/Ps done
        storeK(); storeV();
        __syncthreads();
        if (t + 1 < S_ / 128) { loadK(t + 1); loadV(t + 1); }

        float sacc[2][4][4] = {};
        qk_mma(sacc);

        // p = exp(x - M) * Sinv ; write attn + stage into Ps
        #pragma unroll
        for (int mi = 0; mi < 2; ++mi) {
            #pragma unroll
            for (int ni = 0; ni < 4; ++ni) {
                int r0 = wm + mi * 16 + (lane >> 2);
                int c0 = wn + ni * 8 + (lane & 3) * 2;
                float p0 = __expf(sacc[mi][ni][0] * scale - Mf[mi][0]) * Sf[mi][0];
                float p1 = __expf(sacc[mi][ni][1] * scale - Mf[mi][0]) * Sf[mi][0];
                float p2 = __expf(sacc[mi][ni][2] * scale - Mf[mi][1]) * Sf[mi][1];
                float p3 = __expf(sacc[mi][ni][3] * scale - Mf[mi][1]) * Sf[mi][1];
                *reinterpret_cast<float2*>(attn_b + (size_t)(q0 + r0) * S_ + t * 128 + c0) =
                    make_float2(p0, p1);
                *reinterpret_cast<float2*>(attn_b + (size_t)(q0 + r0 + 8) * S_ + t * 128 + c0) =
                    make_float2(p2, p3);
                Ps[r0 * PS_STRIDE + c0] = f2tf(p0);
                Ps[r0 * PS_STRIDE + c0 + 1] = f2tf(p1);
                Ps[(r0 + 8) * PS_STRIDE + c0] = f2tf(p2);
                Ps[(r0 + 8) * PS_STRIDE + c0 + 1] = f2tf(p3);
            }
        }
        __syncthreads();

        // AV: acco[128 x 64] += P[128 x 128] @ V[128 x 64]
        #pragma unroll
        for (int kk = 0; kk < 16; ++kk) {
            unsigned afr[2][4], bfr[2][2];
            #pragma unroll
            for (int ni = 0; ni < 2; ++ni) {
                int n = wn2 + ni * 8 + (lane >> 2);
                int c = kk * 8 + (lane & 3);
                bfr[ni][0] = Vs[c * QS_STRIDE + n];          // V[k=seq][n=d]
                bfr[ni][1] = Vs[(c + 4) * QS_STRIDE + n];
            }
            #pragma unroll
            for (int mi = 0; mi < 2; ++mi) {
                int r = wm + mi * 16 + (lane >> 2);
                int c = kk * 8 + (lane & 3);
                afr[mi][0] = Ps[r * PS_STRIDE + c];
                afr[mi][1] = Ps[(r + 8) * PS_STRIDE + c];
                afr[mi][2] = Ps[r * PS_STRIDE + c + 4];
                afr[mi][3] = Ps[(r + 8) * PS_STRIDE + c + 4];
            }
            #pragma unroll
            for (int mi = 0; mi < 2; ++mi)
                #pragma unroll
                for (int ni = 0; ni < 2; ++ni)
                    mma8(acco[mi][ni], afr[mi], bfr[ni]);
        }
    }

    // store ctx (already normalized)
    #pragma unroll
    for (int mi = 0; mi < 2; ++mi)
        #pragma unroll
        for (int ni = 0; ni < 2; ++ni)
            #pragma unroll
            for (int e = 0; e < 4; ++e) {
                int row = q0 + wm + mi * 16 + (lane >> 2) + ((e >= 2) ? 8 : 0);
                int d = wn2 + ni * 8 + (lane & 3) * 2 + (e & 1);
                ctx[((size_t)b * S_ + row) * DM + h * DK + d] = acco[mi][ni][e];
            }
}

// ---------------------------------------------------------------------------
extern "C" void kernel_launch(void* const* d_in, const int* in_sizes, int n_in,
                              void* d_out, int out_size)
{
    const float* query = (const float*)d_in[0];
    const float* key   = (const float*)d_in[1];
    const float* value = (const float*)d_in[2];
    const float* w_q = (const float*)d_in[3];
    const float* b_q = (const float*)d_in[4];
    const float* w_k = (const float*)d_in[5];
    const float* b_k = (const float*)d_in[6];
    const float* w_v = (const float*)d_in[7];
    const float* b_v = (const float*)d_in[8];
    const float* w_o = (const float*)d_in[9];
    const float* b_o = (const float*)d_in[10];

    float* out = (float*)d_out;
    float* attn = out + OUT_ELEMS;   // (output, attn) concatenated

    float* Qp; cudaGetSymbolAddress((void**)&Qp, g_Q);
    float* Kp; cudaGetSymbolAddress((void**)&Kp, g_K);
    float* Vp; cudaGetSymbolAddress((void**)&Vp, g_V);
    float* Cp; cudaGetSymbolAddress((void**)&Cp, g_ctx);

    cudaFuncSetAttribute(fused_attn, cudaFuncAttributeMaxDynamicSharedMemorySize,
                         FUSED_SMEM);

    dim3 gproj(DM / 128, (B_ * S_) / 128, 1);   // (8, 64)
    gemm_proj<0><<<gproj, 512>>>(query, w_q, Qp, b_q);
    gemm_proj<0><<<gproj, 512>>>(key,   w_k, Kp, b_k);
    gemm_proj<0><<<gproj, 512>>>(value, w_v, Vp, b_v);

    fused_attn<<<dim3(S_ / 128, B_ * NH), 512, FUSED_SMEM>>>(Qp, Kp, Vp, attn, Cp);

    gemm_proj<1><<<gproj, 512>>>(Cp, w_o, out, b_o);
}

// round 5
// speedup vs baseline: 1.1069x; 1.1069x over previous
#include <cuda_runtime.h>
#include <math.h>

// Problem constants
#define B_ 4
#define S_ 2048
#define DM 1024
#define NH 16
#define DK 64
#define OUT_ELEMS ((size_t)B_ * S_ * DM)            // 8,388,608

// Scratch (no cudaMalloc allowed)
__device__ float g_Q[B_ * NH * S_ * DK];
__device__ float g_K[B_ * NH * S_ * DK];
__device__ float g_V[B_ * NH * S_ * DK];
__device__ float g_ctx[(size_t)B_ * S_ * DM];

__device__ __forceinline__ unsigned f2tf(float x) {
    unsigned u;
    asm("cvt.rna.tf32.f32 %0, %1;" : "=r"(u) : "f"(x));
    return u;
}

__device__ __forceinline__ void mma8(float* c, const unsigned* a, const unsigned* b) {
    asm volatile(
        "mma.sync.aligned.m16n8k8.row.col.f32.tf32.tf32.f32 "
        "{%0,%1,%2,%3}, {%4,%5,%6,%7}, {%8,%9}, {%0,%1,%2,%3};"
        : "+f"(c[0]), "+f"(c[1]), "+f"(c[2]), "+f"(c[3])
        : "r"(a[0]), "r"(a[1]), "r"(a[2]), "r"(a[3]), "r"(b[0]), "r"(b[1]));
}

// Permuted K-dim layout: within each 8-col group, logical col c (w = c&7)
// is stored at position 2*(w&3) + (w>>2). Fragment pairs (c, c+4) become
// adjacent words -> LDS.64, conflict-free when row stride % 32 == 8.

// ---------------------------------------------------------------------------
// Projection GEMM (tf32 MMA): 256 threads, 128x128x32 tile, warp tile 64x32.
// A staged with permuted layout (SA=40), B with SB=136.
// EPI 0 = head-split store, EPI 1 = plain [M,DM] store.
// ---------------------------------------------------------------------------
template<int EPI>
__global__ void __launch_bounds__(256)
gemm_proj(const float* __restrict__ A, const float* __restrict__ W,
          float* __restrict__ C, const float* __restrict__ bias)
{
    constexpr int BM = 128, BN = 128, BK = 32;
    constexpr int SA = 40, SB = BN + 8;      // both % 32 == 8
    __shared__ unsigned As[BM * SA];
    __shared__ unsigned Bs[BK * SB];

    const int tid = threadIdx.x;
    const int lane = tid & 31, wid = tid >> 5;
    const int wm = (wid & 1) * 64, wn = (wid >> 1) * 32;
    const int bm = blockIdx.y * BM, bn = blockIdx.x * BN;

    float acc[4][4][4] = {};
    float4 ra[4], rb[4];

    auto loadA = [&](int k0) {
        #pragma unroll
        for (int i = 0; i < 4; ++i) {
            int f = tid + i * 256;
            int r = f >> 3, c = (f & 7) * 4;
            ra[i] = *reinterpret_cast<const float4*>(A + (size_t)(bm + r) * DM + k0 + c);
        }
    };
    auto loadB = [&](int k0) {
        #pragma unroll
        for (int i = 0; i < 4; ++i) {
            int f = tid + i * 256;
            int r = f >> 5, c = (f & 31) * 4;
            rb[i] = *reinterpret_cast<const float4*>(W + (size_t)(k0 + r) * DM + bn + c);
        }
    };
    auto stage = [&]() {
        #pragma unroll
        for (int i = 0; i < 4; ++i) {
            int f = tid + i * 256;
            int r = f >> 3, c = (f & 7) * 4;
            // permuted store: cols c..c+3 -> positions base+0,2,4,6
            int base = r * SA + ((c >> 3) << 3) + ((c >> 2) & 1);
            As[base]     = f2tf(ra[i].x);
            As[base + 2] = f2tf(ra[i].y);
            As[base + 4] = f2tf(ra[i].z);
            As[base + 6] = f2tf(ra[i].w);
            int r2 = f >> 5, c2 = (f & 31) * 4;
            unsigned* q = &Bs[r2 * SB + c2];
            q[0] = f2tf(rb[i].x); q[1] = f2tf(rb[i].y); q[2] = f2tf(rb[i].z); q[3] = f2tf(rb[i].w);
        }
    };

    loadA(0); loadB(0);
    for (int it = 0; it < DM / BK; ++it) {
        stage();
        __syncthreads();
        if (it + 1 < DM / BK) { loadA((it + 1) * BK); loadB((it + 1) * BK); }

        #pragma unroll
        for (int kk = 0; kk < BK / 8; ++kk) {
            unsigned afr[4][4], bfr[4][2];
            const int cb = kk * 8 + 2 * (lane & 3);
            #pragma unroll
            for (int mi = 0; mi < 4; ++mi) {
                int r = wm + mi * 16 + (lane >> 2);
                uint2 u0 = *reinterpret_cast<const uint2*>(&As[r * SA + cb]);
                uint2 u1 = *reinterpret_cast<const uint2*>(&As[(r + 8) * SA + cb]);
                afr[mi][0] = u0.x; afr[mi][1] = u1.x; afr[mi][2] = u0.y; afr[mi][3] = u1.y;
            }
            #pragma unroll
            for (int ni = 0; ni < 4; ++ni) {
                int n = wn + ni * 8 + (lane >> 2);
                int c = kk * 8 + (lane & 3);
                bfr[ni][0] = Bs[c * SB + n];
                bfr[ni][1] = Bs[(c + 4) * SB + n];
            }
            #pragma unroll
            for (int mi = 0; mi < 4; ++mi)
                #pragma unroll
                for (int ni = 0; ni < 4; ++ni)
                    mma8(acc[mi][ni], afr[mi], bfr[ni]);
        }
        __syncthreads();
    }

    #pragma unroll
    for (int mi = 0; mi < 4; ++mi)
        #pragma unroll
        for (int ni = 0; ni < 4; ++ni)
            #pragma unroll
            for (int e = 0; e < 4; ++e) {
                int m = bm + wm + mi * 16 + (lane >> 2) + ((e >= 2) ? 8 : 0);
                int n = bn + wn + ni * 8 + (lane & 3) * 2 + (e & 1);
                float v = acc[mi][ni][e] + bias[n];
                if (EPI == 0) {
                    int b = m >> 11, s = m & (S_ - 1);
                    int h = n >> 6, d = n & (DK - 1);
                    C[(((size_t)b * NH + h) * S_ + s) * DK + d] = v;
                } else {
                    C[(size_t)m * DM + n] = v;
                }
            }
}

// ---------------------------------------------------------------------------
// Fused attention, 512 threads. Qs/Ks/Ps permuted (LDS.64 fragments);
// Vs linear seq-major (row-strided b-frags, conflict-free).
// ---------------------------------------------------------------------------
#define QS_STRIDE 72          // % 32 == 8
#define PS_STRIDE 136         // % 32 == 8
#define FUSED_SMEM ((3 * 128 * QS_STRIDE + 128 * PS_STRIDE) * 4)   // 180,224 B

__global__ void __launch_bounds__(512, 1)
fused_attn(const float* __restrict__ Q, const float* __restrict__ Km,
           const float* __restrict__ V, float* __restrict__ attn,
           float* __restrict__ ctx)
{
    extern __shared__ unsigned char smem_raw[];
    unsigned* Qs = (unsigned*)smem_raw;                       // [128][72] permuted
    unsigned* Ks = Qs + 128 * QS_STRIDE;                      // [128][72] permuted
    unsigned* Vs = Ks + 128 * QS_STRIDE;                      // [128][72] linear
    unsigned* Ps = Vs + 128 * QS_STRIDE;                      // [128][136] permuted
    float* rowm  = (float*)Ps;          // scratch overlaps Ps (pass 1 only)
    float* rowss = rowm + 128 * 4;
    float* sM    = rowss + 128 * 4;
    float* sSinv = sM + 128;

    const int tid = threadIdx.x;
    const int lane = tid & 31, wid = tid >> 5;
    const int wm = (wid & 3) * 32;
    const int wn = (wid >> 2) * 32;
    const int wn2 = (wid >> 2) * 16;
    const int q0 = blockIdx.x * 128;
    const int bh = blockIdx.y;
    const float scale = 0.125f;

    const float* Qb = Q + (size_t)bh * S_ * DK;
    const float* Kb = Km + (size_t)bh * S_ * DK;
    const float* Vb = V + (size_t)bh * S_ * DK;

    // Load Q tile (128 x 64), permuted store
    #pragma unroll
    for (int i = 0; i < 4; ++i) {
        int f = tid + i * 512;
        int r = f >> 4, c = (f & 15) * 4;
        float4 v = *reinterpret_cast<const float4*>(Qb + (size_t)(q0 + r) * DK + c);
        int base = r * QS_STRIDE + ((c >> 3) << 3) + ((c >> 2) & 1);
        Qs[base]     = f2tf(v.x);
        Qs[base + 2] = f2tf(v.y);
        Qs[base + 4] = f2tf(v.z);
        Qs[base + 6] = f2tf(v.w);
    }

    float4 rk[4], rv[4];
    auto loadK = [&](int t) {
        #pragma unroll
        for (int i = 0; i < 4; ++i) {
            int f = tid + i * 512;
            int r = f >> 4, c = (f & 15) * 4;
            rk[i] = *reinterpret_cast<const float4*>(Kb + (size_t)(t * 128 + r) * DK + c);
        }
    };
    auto storeK = [&]() {
        #pragma unroll
        for (int i = 0; i < 4; ++i) {
            int f = tid + i * 512;
            int r = f >> 4, c = (f & 15) * 4;
            int base = r * QS_STRIDE + ((c >> 3) << 3) + ((c >> 2) & 1);
            Ks[base]     = f2tf(rk[i].x);
            Ks[base + 2] = f2tf(rk[i].y);
            Ks[base + 4] = f2tf(rk[i].z);
            Ks[base + 6] = f2tf(rk[i].w);
        }
    };
    auto loadV = [&](int t) {
        #pragma unroll
        for (int i = 0; i < 4; ++i) {
            int f = tid + i * 512;
            int r = f >> 4, c = (f & 15) * 4;
            rv[i] = *reinterpret_cast<const float4*>(Vb + (size_t)(t * 128 + r) * DK + c);
        }
    };
    auto storeV = [&]() {
        #pragma unroll
        for (int i = 0; i < 4; ++i) {
            int f = tid + i * 512;
            int r = f >> 4, c = (f & 15) * 4;
            uint4 u;
            u.x = f2tf(rv[i].x); u.y = f2tf(rv[i].y);
            u.z = f2tf(rv[i].z); u.w = f2tf(rv[i].w);
            *reinterpret_cast<uint4*>(&Vs[r * QS_STRIDE + c]) = u;
        }
    };

    auto qk_mma = [&](float sacc[2][4][4]) {
        #pragma unroll
        for (int kk = 0; kk < 8; ++kk) {
            unsigned afr[2][4], bfr[4][2];
            const int cb = kk * 8 + 2 * (lane & 3);
            #pragma unroll
            for (int mi = 0; mi < 2; ++mi) {
                int r = wm + mi * 16 + (lane >> 2);
                uint2 u0 = *reinterpret_cast<const uint2*>(&Qs[r * QS_STRIDE + cb]);
                uint2 u1 = *reinterpret_cast<const uint2*>(&Qs[(r + 8) * QS_STRIDE + cb]);
                afr[mi][0] = u0.x; afr[mi][1] = u1.x; afr[mi][2] = u0.y; afr[mi][3] = u1.y;
            }
            #pragma unroll
            for (int ni = 0; ni < 4; ++ni) {
                int n = wn + ni * 8 + (lane >> 2);
                uint2 v = *reinterpret_cast<const uint2*>(&Ks[n * QS_STRIDE + cb]);
                bfr[ni][0] = v.x; bfr[ni][1] = v.y;
            }
            #pragma unroll
            for (int mi = 0; mi < 2; ++mi)
                #pragma unroll
                for (int ni = 0; ni < 4; ++ni)
                    mma8(sacc[mi][ni], afr[mi], bfr[ni]);
        }
    };

    float mreg[2][2], sreg[2][2];
    #pragma unroll
    for (int mi = 0; mi < 2; ++mi)
        #pragma unroll
        for (int e = 0; e < 2; ++e) { mreg[mi][e] = -INFINITY; sreg[mi][e] = 0.f; }

    // ---------------- Pass 1: row max + sum ----------------
    loadK(0);
    for (int t = 0; t < S_ / 128; ++t) {
        if (t) __syncthreads();
        storeK();
        __syncthreads();
        if (t + 1 < S_ / 128) loadK(t + 1);

        float sacc[2][4][4] = {};
        qk_mma(sacc);

        #pragma unroll
        for (int mi = 0; mi < 2; ++mi)
            #pragma unroll
            for (int e = 0; e < 2; ++e) {
                float lm = -INFINITY;
                #pragma unroll
                for (int ni = 0; ni < 4; ++ni)
                    lm = fmaxf(lm, fmaxf(sacc[mi][ni][e * 2], sacc[mi][ni][e * 2 + 1]));
                lm *= scale;
                float nm = fmaxf(mreg[mi][e], lm);
                float add = 0.f;
                #pragma unroll
                for (int ni = 0; ni < 4; ++ni) {
                    add += __expf(sacc[mi][ni][e * 2] * scale - nm);
                    add += __expf(sacc[mi][ni][e * 2 + 1] * scale - nm);
                }
                sreg[mi][e] = sreg[mi][e] * __expf(mreg[mi][e] - nm) + add;
                mreg[mi][e] = nm;
            }
    }

    // ---------------- Cross-lane / cross-warp reduction ----------------
    #pragma unroll
    for (int mi = 0; mi < 2; ++mi)
        #pragma unroll
        for (int e = 0; e < 2; ++e) {
            float m = mreg[mi][e], s = sreg[mi][e];
            #pragma unroll
            for (int off = 1; off <= 2; off <<= 1) {
                float om = __shfl_xor_sync(0xFFFFFFFFu, m, off);
                float os = __shfl_xor_sync(0xFFFFFFFFu, s, off);
                float nm = fmaxf(m, om);
                s = s * __expf(m - nm) + os * __expf(om - nm);
                m = nm;
            }
            mreg[mi][e] = m; sreg[mi][e] = s;
        }
    __syncthreads();
    if ((lane & 3) == 0) {
        int g = wid >> 2;
        #pragma unroll
        for (int mi = 0; mi < 2; ++mi)
            #pragma unroll
            for (int e = 0; e < 2; ++e) {
                int r = wm + mi * 16 + (lane >> 2) + e * 8;
                rowm[r * 4 + g] = mreg[mi][e];
                rowss[r * 4 + g] = sreg[mi][e];
            }
    }
    __syncthreads();
    if (tid < 128) {
        float M = -INFINITY;
        #pragma unroll
        for (int g = 0; g < 4; ++g) M = fmaxf(M, rowm[tid * 4 + g]);
        float S = 0.f;
        #pragma unroll
        for (int g = 0; g < 4; ++g) S += rowss[tid * 4 + g] * __expf(rowm[tid * 4 + g] - M);
        sM[tid] = M;
        sSinv[tid] = 1.0f / S;
    }
    __syncthreads();

    float Mf[2][2], Sf[2][2];
    #pragma unroll
    for (int mi = 0; mi < 2; ++mi)
        #pragma unroll
        for (int e = 0; e < 2; ++e) {
            int r = wm + mi * 16 + (lane >> 2) + e * 8;
            Mf[mi][e] = sM[r];
            Sf[mi][e] = sSinv[r];
        }

    // ---------------- Pass 2: recompute, write attn, accumulate P@V ------
    float acco[2][2][4] = {};
    float* attn_b = attn + (size_t)bh * S_ * S_;
    const int b = bh >> 4, h = bh & (NH - 1);

    loadK(0); loadV(0);
    for (int t = 0; t < S_ / 128; ++t) {
        if (t) __syncthreads();
        storeK(); storeV();
        __syncthreads();
        if (t + 1 < S_ / 128) { loadK(t + 1); loadV(t + 1); }

        float sacc[2][4][4] = {};
        qk_mma(sacc);

        // p = exp(x - M) * Sinv ; write attn + permuted stage into Ps
        #pragma unroll
        for (int mi = 0; mi < 2; ++mi) {
            #pragma unroll
            for (int ni = 0; ni < 4; ++ni) {
                int r0 = wm + mi * 16 + (lane >> 2);
                int c0 = wn + ni * 8 + (lane & 3) * 2;
                float p0 = __expf(sacc[mi][ni][0] * scale - Mf[mi][0]) * Sf[mi][0];
                float p1 = __expf(sacc[mi][ni][1] * scale - Mf[mi][0]) * Sf[mi][0];
                float p2 = __expf(sacc[mi][ni][2] * scale - Mf[mi][1]) * Sf[mi][1];
                float p3 = __expf(sacc[mi][ni][3] * scale - Mf[mi][1]) * Sf[mi][1];
                *reinterpret_cast<float2*>(attn_b + (size_t)(q0 + r0) * S_ + t * 128 + c0) =
                    make_float2(p0, p1);
                *reinterpret_cast<float2*>(attn_b + (size_t)(q0 + r0 + 8) * S_ + t * 128 + c0) =
                    make_float2(p2, p3);
                int w0 = c0 & 7;
                int colp = ((c0 >> 3) << 3) + 2 * (w0 & 3) + (w0 >> 2);
                Ps[r0 * PS_STRIDE + colp] = f2tf(p0);
                Ps[r0 * PS_STRIDE + colp + 2] = f2tf(p1);
                Ps[(r0 + 8) * PS_STRIDE + colp] = f2tf(p2);
                Ps[(r0 + 8) * PS_STRIDE + colp + 2] = f2tf(p3);
            }
        }
        __syncthreads();

        // AV: acco += P[128x128] @ V[128x64]
        #pragma unroll
        for (int kk = 0; kk < 16; ++kk) {
            unsigned afr[2][4], bfr[2][2];
            const int cb = kk * 8 + 2 * (lane & 3);
            const int cv = kk * 8 + (lane & 3);
            #pragma unroll
            for (int ni = 0; ni < 2; ++ni) {
                int n = wn2 + ni * 8 + (lane >> 2);
                bfr[ni][0] = Vs[cv * QS_STRIDE + n];
                bfr[ni][1] = Vs[(cv + 4) * QS_STRIDE + n];
            }
            #pragma unroll
            for (int mi = 0; mi < 2; ++mi) {
                int r = wm + mi * 16 + (lane >> 2);
                uint2 u0 = *reinterpret_cast<const uint2*>(&Ps[r * PS_STRIDE + cb]);
                uint2 u1 = *reinterpret_cast<const uint2*>(&Ps[(r + 8) * PS_STRIDE + cb]);
                afr[mi][0] = u0.x; afr[mi][1] = u1.x; afr[mi][2] = u0.y; afr[mi][3] = u1.y;
            }
            #pragma unroll
            for (int mi = 0; mi < 2; ++mi)
                #pragma unroll
                for (int ni = 0; ni < 2; ++ni)
                    mma8(acco[mi][ni], afr[mi], bfr[ni]);
        }
    }

    // store ctx (already normalized)
    #pragma unroll
    for (int mi = 0; mi < 2; ++mi)
        #pragma unroll
        for (int ni = 0; ni < 2; ++ni)
            #pragma unroll
            for (int e = 0; e < 4; ++e) {
                int row = q0 + wm + mi * 16 + (lane >> 2) + ((e >= 2) ? 8 : 0);
                int d = wn2 + ni * 8 + (lane & 3) * 2 + (e & 1);
                ctx[((size_t)b * S_ + row) * DM + h * DK + d] = acco[mi][ni][e];
            }
}

// ---------------------------------------------------------------------------
extern "C" void kernel_launch(void* const* d_in, const int* in_sizes, int n_in,
                              void* d_out, int out_size)
{
    const float* query = (const float*)d_in[0];
    const float* key   = (const float*)d_in[1];
    const float* value = (const float*)d_in[2];
    const float* w_q = (const float*)d_in[3];
    const float* b_q = (const float*)d_in[4];
    const float* w_k = (const float*)d_in[5];
    const float* b_k = (const float*)d_in[6];
    const float* w_v = (const float*)d_in[7];
    const float* b_v = (const float*)d_in[8];
    const float* w_o = (const float*)d_in[9];
    const float* b_o = (const float*)d_in[10];

    float* out = (float*)d_out;
    float* attn = out + OUT_ELEMS;   // (output, attn) concatenated

    float* Qp; cudaGetSymbolAddress((void**)&Qp, g_Q);
    float* Kp; cudaGetSymbolAddress((void**)&Kp, g_K);
    float* Vp; cudaGetSymbolAddress((void**)&Vp, g_V);
    float* Cp; cudaGetSymbolAddress((void**)&Cp, g_ctx);

    cudaFuncSetAttribute(fused_attn, cudaFuncAttributeMaxDynamicSharedMemorySize,
                         FUSED_SMEM);

    dim3 gproj(DM / 128, (B_ * S_) / 128, 1);   // (8, 64)
    gemm_proj<0><<<gproj, 256>>>(query, w_q, Qp, b_q);
    gemm_proj<0><<<gproj, 256>>>(key,   w_k, Kp, b_k);
    gemm_proj<0><<<gproj, 256>>>(value, w_v, Vp, b_v);

    fused_attn<<<dim3(S_ / 128, B_ * NH), 512, FUSED_SMEM>>>(Qp, Kp, Vp, attn, Cp);

    gemm_proj<1><<<gproj, 256>>>(Cp, w_o, out, b_o);
}

// round 6
// speedup vs baseline: 1.2135x; 1.0963x over previous
#include <cuda_runtime.h>
#include <math.h>

// Problem constants
#define B_ 4
#define S_ 2048
#define DM 1024
#define NH 16
#define DK 64
#define OUT_ELEMS ((size_t)B_ * S_ * DM)            // 8,388,608

// Scratch (no cudaMalloc allowed)
__device__ float g_Q[B_ * NH * S_ * DK];
__device__ float g_K[B_ * NH * S_ * DK];
__device__ float g_V[B_ * NH * S_ * DK];
__device__ float g_ctx[(size_t)B_ * S_ * DM];

__device__ __forceinline__ unsigned f2tf(float x) {
    unsigned u;
    asm("cvt.rna.tf32.f32 %0, %1;" : "=r"(u) : "f"(x));
    return u;
}

__device__ __forceinline__ void mma8(float* c, const unsigned* a, const unsigned* b) {
    asm volatile(
        "mma.sync.aligned.m16n8k8.row.col.f32.tf32.tf32.f32 "
        "{%0,%1,%2,%3}, {%4,%5,%6,%7}, {%8,%9}, {%0,%1,%2,%3};"
        : "+f"(c[0]), "+f"(c[1]), "+f"(c[2]), "+f"(c[3])
        : "r"(a[0]), "r"(a[1]), "r"(a[2]), "r"(a[3]), "r"(b[0]), "r"(b[1]));
}

__device__ __forceinline__ void cpasync16(unsigned saddr, const void* g) {
    asm volatile("cp.async.ca.shared.global [%0], [%1], 16;" :: "r"(saddr), "l"(g));
}
__device__ __forceinline__ void cp_commit() {
    asm volatile("cp.async.commit_group;");
}
__device__ __forceinline__ void cp_wait(bool keep_one) {
    if (keep_one) asm volatile("cp.async.wait_group 1;");
    else          asm volatile("cp.async.wait_group 0;");
}

// ---------------------------------------------------------------------------
// Projection GEMM (round-3 config): 256 threads, 128x128x32, warp tile 64x32.
// EPI 0 = head-split store, EPI 1 = plain [M,DM] store.
// ---------------------------------------------------------------------------
template<int EPI>
__global__ void __launch_bounds__(256)
gemm_proj(const float* __restrict__ A, const float* __restrict__ W,
          float* __restrict__ C, const float* __restrict__ bias)
{
    constexpr int BM = 128, BN = 128, BK = 32;
    constexpr int SA = BK + 4, SB = BN + 8;
    __shared__ unsigned As[BM * SA];
    __shared__ unsigned Bs[BK * SB];

    const int tid = threadIdx.x;
    const int lane = tid & 31, wid = tid >> 5;
    const int wm = (wid & 1) * 64, wn = (wid >> 1) * 32;
    const int bm = blockIdx.y * BM, bn = blockIdx.x * BN;

    float acc[4][4][4] = {};
    float4 ra[4], rb[4];

    auto loadA = [&](int k0) {
        #pragma unroll
        for (int i = 0; i < 4; ++i) {
            int f = tid + i * 256;
            int r = f >> 3, c = (f & 7) * 4;
            ra[i] = *reinterpret_cast<const float4*>(A + (size_t)(bm + r) * DM + k0 + c);
        }
    };
    auto loadB = [&](int k0) {
        #pragma unroll
        for (int i = 0; i < 4; ++i) {
            int f = tid + i * 256;
            int r = f >> 5, c = (f & 31) * 4;
            rb[i] = *reinterpret_cast<const float4*>(W + (size_t)(k0 + r) * DM + bn + c);
        }
    };
    auto stage = [&]() {
        #pragma unroll
        for (int i = 0; i < 4; ++i) {
            int f = tid + i * 256;
            int r = f >> 3, c = (f & 7) * 4;
            unsigned* p = &As[r * SA + c];
            p[0] = f2tf(ra[i].x); p[1] = f2tf(ra[i].y); p[2] = f2tf(ra[i].z); p[3] = f2tf(ra[i].w);
            int r2 = f >> 5, c2 = (f & 31) * 4;
            unsigned* q = &Bs[r2 * SB + c2];
            q[0] = f2tf(rb[i].x); q[1] = f2tf(rb[i].y); q[2] = f2tf(rb[i].z); q[3] = f2tf(rb[i].w);
        }
    };

    loadA(0); loadB(0);
    for (int it = 0; it < DM / BK; ++it) {
        stage();
        __syncthreads();
        if (it + 1 < DM / BK) { loadA((it + 1) * BK); loadB((it + 1) * BK); }

        #pragma unroll
        for (int kk = 0; kk < BK / 8; ++kk) {
            unsigned afr[4][4], bfr[4][2];
            #pragma unroll
            for (int mi = 0; mi < 4; ++mi) {
                int r = wm + mi * 16 + (lane >> 2);
                int c = kk * 8 + (lane & 3);
                afr[mi][0] = As[r * SA + c];
                afr[mi][1] = As[(r + 8) * SA + c];
                afr[mi][2] = As[r * SA + c + 4];
                afr[mi][3] = As[(r + 8) * SA + c + 4];
            }
            #pragma unroll
            for (int ni = 0; ni < 4; ++ni) {
                int n = wn + ni * 8 + (lane >> 2);
                int c = kk * 8 + (lane & 3);
                bfr[ni][0] = Bs[c * SB + n];
                bfr[ni][1] = Bs[(c + 4) * SB + n];
            }
            #pragma unroll
            for (int mi = 0; mi < 4; ++mi)
                #pragma unroll
                for (int ni = 0; ni < 4; ++ni)
                    mma8(acc[mi][ni], afr[mi], bfr[ni]);
        }
        __syncthreads();
    }

    #pragma unroll
    for (int mi = 0; mi < 4; ++mi)
        #pragma unroll
        for (int ni = 0; ni < 4; ++ni)
            #pragma unroll
            for (int e = 0; e < 4; ++e) {
                int m = bm + wm + mi * 16 + (lane >> 2) + ((e >= 2) ? 8 : 0);
                int n = bn + wn + ni * 8 + (lane & 3) * 2 + (e & 1);
                float v = acc[mi][ni][e] + bias[n];
                if (EPI == 0) {
                    int b = m >> 11, s = m & (S_ - 1);
                    int h = n >> 6, d = n & (DK - 1);
                    C[(((size_t)b * NH + h) * S_ + s) * DK + d] = v;
                } else {
                    C[(size_t)m * DM + n] = v;
                }
            }
}

// ---------------------------------------------------------------------------
// Fused attention, 512 threads.
// Qs: tf32(rna) permuted layout (stride 72), loaded once.
// K/V: raw f32 via cp.async double-buffer (stride 68), HW-truncated tf32 in MMA
//      (same representation in both passes -> identical scores).
// Pass 2: P exchanged acc->A-frag via warp shuffles (no Ps smem); AV k-split
//      across the 4 n-warp-groups (full d=64 each), cross-warp reduce at end.
// ---------------------------------------------------------------------------
#define QS_STRIDE 72
#define KV_STRIDE 68
#define OFF_Q   0
#define Q_BYTES (128 * QS_STRIDE * 4)                 // 36,864
#define KB_BYTES (128 * KV_STRIDE * 4)                // 34,816
#define OFF_K   (OFF_Q + Q_BYTES)                     // 36,864
#define OFF_V   (OFF_K + 2 * KB_BYTES)                // 106,496
#define OFF_SM  (OFF_V + 2 * KB_BYTES)                // 176,128
#define OFF_SS  (OFF_SM + 512)                        // 176,640
#define FUSED_SMEM (OFF_SS + 512)                     // 177,152

__global__ void __launch_bounds__(512, 1)
fused_attn(const float* __restrict__ Q, const float* __restrict__ Km,
           const float* __restrict__ V, float* __restrict__ attn,
           float* __restrict__ ctx)
{
    extern __shared__ unsigned char smem_raw[];
    unsigned* Qs = (unsigned*)(smem_raw + OFF_Q);
    float* sM    = (float*)(smem_raw + OFF_SM);
    float* sSinv = (float*)(smem_raw + OFF_SS);
    // inter-pass reduction scratch lives in the (then-idle) V buffers
    float* rowm  = (float*)(smem_raw + OFF_V);
    float* rowss = rowm + 128 * 4;

    const unsigned sb = (unsigned)__cvta_generic_to_shared(smem_raw);
    const int tid = threadIdx.x;
    const int lane = tid & 31, wid = tid >> 5;
    const int wm = (wid & 3) * 32;          // warp q-rows
    const int wn = (wid >> 2) * 32;         // warp score cols (and AV k-range)
    const int q0 = blockIdx.x * 128;
    const int bh = blockIdx.y;
    const float scale = 0.125f;

    const float* Qb = Q + (size_t)bh * S_ * DK;
    const float* Kb = Km + (size_t)bh * S_ * DK;
    const float* Vb = V + (size_t)bh * S_ * DK;

    // Load Q tile (128 x 64), rna-tf32, permuted layout for LDS.64 a-frags
    #pragma unroll
    for (int i = 0; i < 4; ++i) {
        int f = tid + i * 512;
        int r = f >> 4, c = (f & 15) * 4;
        float4 v = *reinterpret_cast<const float4*>(Qb + (size_t)(q0 + r) * DK + c);
        int base = r * QS_STRIDE + ((c >> 3) << 3) + ((c >> 2) & 1);
        Qs[base]     = f2tf(v.x);
        Qs[base + 2] = f2tf(v.y);
        Qs[base + 4] = f2tf(v.z);
        Qs[base + 6] = f2tf(v.w);
    }

    auto issueK = [&](int t) {
        #pragma unroll
        for (int i = 0; i < 4; ++i) {
            int f = tid + i * 512;
            int r = f >> 4, c4 = (f & 15) * 4;
            unsigned dst = sb + OFF_K + (t & 1) * KB_BYTES + (r * KV_STRIDE + c4) * 4;
            cpasync16(dst, Kb + (size_t)(t * 128 + r) * DK + c4);
        }
    };
    auto issueV = [&](int t) {
        #pragma unroll
        for (int i = 0; i < 4; ++i) {
            int f = tid + i * 512;
            int r = f >> 4, c4 = (f & 15) * 4;
            unsigned dst = sb + OFF_V + (t & 1) * KB_BYTES + (r * KV_STRIDE + c4) * 4;
            cpasync16(dst, Vb + (size_t)(t * 128 + r) * DK + c4);
        }
    };

    // QK^T MMA on current K buffer -> sacc
    auto qk_mma = [&](float sacc[2][4][4], const unsigned* Kc) {
        #pragma unroll
        for (int kk = 0; kk < 8; ++kk) {
            unsigned afr[2][4], bfr[4][2];
            const int cbq = kk * 8 + 2 * (lane & 3);
            #pragma unroll
            for (int mi = 0; mi < 2; ++mi) {
                int r = wm + mi * 16 + (lane >> 2);
                uint2 u0 = *reinterpret_cast<const uint2*>(&Qs[r * QS_STRIDE + cbq]);
                uint2 u1 = *reinterpret_cast<const uint2*>(&Qs[(r + 8) * QS_STRIDE + cbq]);
                afr[mi][0] = u0.x; afr[mi][1] = u1.x; afr[mi][2] = u0.y; afr[mi][3] = u1.y;
            }
            const int c = kk * 8 + (lane & 3);
            #pragma unroll
            for (int ni = 0; ni < 4; ++ni) {
                int n = wn + ni * 8 + (lane >> 2);
                bfr[ni][0] = Kc[n * KV_STRIDE + c];
                bfr[ni][1] = Kc[n * KV_STRIDE + c + 4];
            }
            #pragma unroll
            for (int mi = 0; mi < 2; ++mi)
                #pragma unroll
                for (int ni = 0; ni < 4; ++ni)
                    mma8(sacc[mi][ni], afr[mi], bfr[ni]);
        }
    };

    float mreg[2][2], sreg[2][2];
    #pragma unroll
    for (int mi = 0; mi < 2; ++mi)
        #pragma unroll
        for (int e = 0; e < 2; ++e) { mreg[mi][e] = -INFINITY; sreg[mi][e] = 0.f; }

    // ---------------- Pass 1: row max + sum ----------------
    issueK(0); cp_commit();
    for (int t = 0; t < S_ / 128; ++t) {
        __syncthreads();                         // prior readers of buf[(t+1)&1] done
        if (t + 1 < S_ / 128) { issueK(t + 1); cp_commit(); }
        cp_wait(t + 1 < S_ / 128);
        __syncthreads();
        const unsigned* Kc = (const unsigned*)(smem_raw + OFF_K + (t & 1) * KB_BYTES);

        float sacc[2][4][4] = {};
        qk_mma(sacc, Kc);

        #pragma unroll
        for (int mi = 0; mi < 2; ++mi)
            #pragma unroll
            for (int e = 0; e < 2; ++e) {
                float lm = -INFINITY;
                #pragma unroll
                for (int ni = 0; ni < 4; ++ni)
                    lm = fmaxf(lm, fmaxf(sacc[mi][ni][e * 2], sacc[mi][ni][e * 2 + 1]));
                lm *= scale;
                float nm = fmaxf(mreg[mi][e], lm);
                float add = 0.f;
                #pragma unroll
                for (int ni = 0; ni < 4; ++ni) {
                    add += __expf(sacc[mi][ni][e * 2] * scale - nm);
                    add += __expf(sacc[mi][ni][e * 2 + 1] * scale - nm);
                }
                sreg[mi][e] = sreg[mi][e] * __expf(mreg[mi][e] - nm) + add;
                mreg[mi][e] = nm;
            }
    }

    // ---------------- Cross-lane / cross-warp reduction ----------------
    #pragma unroll
    for (int mi = 0; mi < 2; ++mi)
        #pragma unroll
        for (int e = 0; e < 2; ++e) {
            float m = mreg[mi][e], s = sreg[mi][e];
            #pragma unroll
            for (int off = 1; off <= 2; off <<= 1) {
                float om = __shfl_xor_sync(0xFFFFFFFFu, m, off);
                float os = __shfl_xor_sync(0xFFFFFFFFu, s, off);
                float nm = fmaxf(m, om);
                s = s * __expf(m - nm) + os * __expf(om - nm);
                m = nm;
            }
            mreg[mi][e] = m; sreg[mi][e] = s;
        }
    __syncthreads();
    if ((lane & 3) == 0) {
        int g = wid >> 2;
        #pragma unroll
        for (int mi = 0; mi < 2; ++mi)
            #pragma unroll
            for (int e = 0; e < 2; ++e) {
                int r = wm + mi * 16 + (lane >> 2) + e * 8;
                rowm[r * 4 + g] = mreg[mi][e];
                rowss[r * 4 + g] = sreg[mi][e];
            }
    }
    __syncthreads();
    if (tid < 128) {
        float M = -INFINITY;
        #pragma unroll
        for (int g = 0; g < 4; ++g) M = fmaxf(M, rowm[tid * 4 + g]);
        float S = 0.f;
        #pragma unroll
        for (int g = 0; g < 4; ++g) S += rowss[tid * 4 + g] * __expf(rowm[tid * 4 + g] - M);
        sM[tid] = M;
        sSinv[tid] = 1.0f / S;
    }
    __syncthreads();

    float Mf[2][2], Sf[2][2];
    #pragma unroll
    for (int mi = 0; mi < 2; ++mi)
        #pragma unroll
        for (int e = 0; e < 2; ++e) {
            int r = wm + mi * 16 + (lane >> 2) + e * 8;
            Mf[mi][e] = sM[r];
            Sf[mi][e] = sSinv[r];
        }

    // ---------------- Pass 2: recompute, write attn, partial P@V ----------
    float acco[2][8][4] = {};     // rows: warp's 32 q-rows; cols: full d=64
    float* attn_b = attn + (size_t)bh * S_ * S_;
    const int b = bh >> 4, h = bh & (NH - 1);
    const unsigned FULL = 0xFFFFFFFFu;
    const int src1 = (lane & ~3) | ((lane & 3) >> 1);
    const int src2 = src1 + 2;
    const bool sel_hi = (lane & 1);

    __syncthreads();              // rowm/rowss reads done before V cp.async overwrites
    issueK(0); issueV(0); cp_commit();
    for (int t = 0; t < S_ / 128; ++t) {
        __syncthreads();
        if (t + 1 < S_ / 128) { issueK(t + 1); issueV(t + 1); cp_commit(); }
        cp_wait(t + 1 < S_ / 128);
        __syncthreads();
        const unsigned* Kc = (const unsigned*)(smem_raw + OFF_K + (t & 1) * KB_BYTES);
        const unsigned* Vc = (const unsigned*)(smem_raw + OFF_V + (t & 1) * KB_BYTES);

        float sacc[2][4][4] = {};
        qk_mma(sacc, Kc);

        // per ni (== AV kk'): P, attn write, shuffle-exchange, AV MMA
        #pragma unroll
        for (int ni = 0; ni < 4; ++ni) {
            unsigned afr2[2][4];
            #pragma unroll
            for (int mi = 0; mi < 2; ++mi) {
                int r0 = wm + mi * 16 + (lane >> 2);
                int c0 = wn + ni * 8 + 2 * (lane & 3);
                float p0 = __expf(sacc[mi][ni][0] * scale - Mf[mi][0]) * Sf[mi][0];
                float p1 = __expf(sacc[mi][ni][1] * scale - Mf[mi][0]) * Sf[mi][0];
                float p2 = __expf(sacc[mi][ni][2] * scale - Mf[mi][1]) * Sf[mi][1];
                float p3 = __expf(sacc[mi][ni][3] * scale - Mf[mi][1]) * Sf[mi][1];
                *reinterpret_cast<float2*>(attn_b + (size_t)(q0 + r0) * S_ + t * 128 + c0) =
                    make_float2(p0, p1);
                *reinterpret_cast<float2*>(attn_b + (size_t)(q0 + r0 + 8) * S_ + t * 128 + c0) =
                    make_float2(p2, p3);
                unsigned u0 = f2tf(p0), u1 = f2tf(p1), u2 = f2tf(p2), u3 = f2tf(p3);
                // acc layout -> A-frag layout (16x8 block), pure lane permutation
                unsigned t00 = __shfl_sync(FULL, u0, src1);
                unsigned t01 = __shfl_sync(FULL, u1, src1);
                unsigned t10 = __shfl_sync(FULL, u2, src1);
                unsigned t11 = __shfl_sync(FULL, u3, src1);
                unsigned t20 = __shfl_sync(FULL, u0, src2);
                unsigned t21 = __shfl_sync(FULL, u1, src2);
                unsigned t30 = __shfl_sync(FULL, u2, src2);
                unsigned t31 = __shfl_sync(FULL, u3, src2);
                afr2[mi][0] = sel_hi ? t01 : t00;
                afr2[mi][1] = sel_hi ? t11 : t10;
                afr2[mi][2] = sel_hi ? t21 : t20;
                afr2[mi][3] = sel_hi ? t31 : t30;
            }
            const int cb = wn + ni * 8;       // this warp's 8 V seq-rows
            #pragma unroll
            for (int ni2 = 0; ni2 < 8; ++ni2) {
                unsigned bfr[2];
                bfr[0] = Vc[(cb + (lane & 3)) * KV_STRIDE + ni2 * 8 + (lane >> 2)];
                bfr[1] = Vc[(cb + (lane & 3) + 4) * KV_STRIDE + ni2 * 8 + (lane >> 2)];
                mma8(acco[0][ni2], afr2[0], bfr);
                mma8(acco[1][ni2], afr2[1], bfr);
            }
        }
    }

    // ---------------- Cross-warp acco reduction (k-split x4) --------------
    __syncthreads();
    float* red = (float*)(smem_raw + OFF_K);   // 512*64*4 = 131072 <= 2*KB+... OK
    {
        int base = tid * 64;
        #pragma unroll
        for (int mi = 0; mi < 2; ++mi)
            #pragma unroll
            for (int ni2 = 0; ni2 < 8; ++ni2)
                #pragma unroll
                for (int e = 0; e < 4; ++e)
                    red[base + mi * 32 + ni2 * 4 + e] = acco[mi][ni2][e];
    }
    __syncthreads();
    {
        const int wmg = wid & 3, gg = wid >> 2;
        #pragma unroll
        for (int nn = 0; nn < 2; ++nn) {
            int ni2 = gg * 2 + nn;
            #pragma unroll
            for (int mi = 0; mi < 2; ++mi)
                #pragma unroll
                for (int e = 0; e < 4; ++e) {
                    float s = 0.f;
                    #pragma unroll
                    for (int g = 0; g < 4; ++g)
                        s += red[((4 * g + wmg) * 32 + lane) * 64 + mi * 32 + ni2 * 4 + e];
                    int row = q0 + wmg * 32 + mi * 16 + (lane >> 2) + ((e >= 2) ? 8 : 0);
                    int d = ni2 * 8 + (lane & 3) * 2 + (e & 1);
                    ctx[((size_t)b * S_ + row) * DM + h * DK + d] = s;
                }
        }
    }
}

// ---------------------------------------------------------------------------
extern "C" void kernel_launch(void* const* d_in, const int* in_sizes, int n_in,
                              void* d_out, int out_size)
{
    const float* query = (const float*)d_in[0];
    const float* key   = (const float*)d_in[1];
    const float* value = (const float*)d_in[2];
    const float* w_q = (const float*)d_in[3];
    const float* b_q = (const float*)d_in[4];
    const float* w_k = (const float*)d_in[5];
    const float* b_k = (const float*)d_in[6];
    const float* w_v = (const float*)d_in[7];
    const float* b_v = (const float*)d_in[8];
    const float* w_o = (const float*)d_in[9];
    const float* b_o = (const float*)d_in[10];

    float* out = (float*)d_out;
    float* attn = out + OUT_ELEMS;   // (output, attn) concatenated

    float* Qp; cudaGetSymbolAddress((void**)&Qp, g_Q);
    float* Kp; cudaGetSymbolAddress((void**)&Kp, g_K);
    float* Vp; cudaGetSymbolAddress((void**)&Vp, g_V);
    float* Cp; cudaGetSymbolAddress((void**)&Cp, g_ctx);

    cudaFuncSetAttribute(fused_attn, cudaFuncAttributeMaxDynamicSharedMemorySize,
                         FUSED_SMEM);

    dim3 gproj(DM / 128, (B_ * S_) / 128, 1);   // (8, 64)
    gemm_proj<0><<<gproj, 256>>>(query, w_q, Qp, b_q);
    gemm_proj<0><<<gproj, 256>>>(key,   w_k, Kp, b_k);
    gemm_proj<0><<<gproj, 256>>>(value, w_v, Vp, b_v);

    fused_attn<<<dim3(S_ / 128, B_ * NH), 512, FUSED_SMEM>>>(Qp, Kp, Vp, attn, Cp);

    gemm_proj<1><<<gproj, 256>>>(Cp, w_o, out, b_o);
}

// round 7
// speedup vs baseline: 1.2714x; 1.0477x over previous
#include <cuda_runtime.h>
#include <math.h>

// Problem constants
#define B_ 4
#define S_ 2048
#define DM 1024
#define NH 16
#define DK 64
#define OUT_ELEMS ((size_t)B_ * S_ * DM)            // 8,388,608

// Scratch (no cudaMalloc allowed)
__device__ float g_Q[B_ * NH * S_ * DK];
__device__ float g_K[B_ * NH * S_ * DK];
__device__ float g_V[B_ * NH * S_ * DK];
__device__ float g_ctx[(size_t)B_ * S_ * DM];

__device__ __forceinline__ unsigned f2tf(float x) {
    unsigned u;
    asm("cvt.rna.tf32.f32 %0, %1;" : "=r"(u) : "f"(x));
    return u;
}

__device__ __forceinline__ void mma8(float* c, const unsigned* a, const unsigned* b) {
    asm volatile(
        "mma.sync.aligned.m16n8k8.row.col.f32.tf32.tf32.f32 "
        "{%0,%1,%2,%3}, {%4,%5,%6,%7}, {%8,%9}, {%0,%1,%2,%3};"
        : "+f"(c[0]), "+f"(c[1]), "+f"(c[2]), "+f"(c[3])
        : "r"(a[0]), "r"(a[1]), "r"(a[2]), "r"(a[3]), "r"(b[0]), "r"(b[1]));
}

__device__ __forceinline__ void cpasync16(unsigned saddr, const void* g) {
    asm volatile("cp.async.ca.shared.global [%0], [%1], 16;" :: "r"(saddr), "l"(g));
}
__device__ __forceinline__ void cp_commit() {
    asm volatile("cp.async.commit_group;");
}
__device__ __forceinline__ void cp_wait(bool keep_one) {
    if (keep_one) asm volatile("cp.async.wait_group 1;");
    else          asm volatile("cp.async.wait_group 0;");
}

// ---------------------------------------------------------------------------
// Projection GEMM: 256 threads, 128x128x32, warp tile 64x32.
// cp.async double-buffered raw f32 (HW tf32 truncation in MMA); 2 CTAs/SM.
// EPI 0 = head-split store, EPI 1 = plain [M,DM] store.
// ---------------------------------------------------------------------------
#define PSA 36
#define PSB 136
#define PROJ_A_WORDS (128 * PSA)                 // 4608
#define PROJ_B_WORDS (32 * PSB)                  // 4352
#define PROJ_SMEM ((2 * PROJ_A_WORDS + 2 * PROJ_B_WORDS) * 4)   // 71,680 B

template<int EPI>
__global__ void __launch_bounds__(256, 2)
gemm_proj(const float* __restrict__ A, const float* __restrict__ W,
          float* __restrict__ C, const float* __restrict__ bias)
{
    extern __shared__ float psm[];
    const unsigned sb = (unsigned)__cvta_generic_to_shared(psm);

    const int tid = threadIdx.x;
    const int lane = tid & 31, wid = tid >> 5;
    const int wm = (wid & 1) * 64, wn = (wid >> 1) * 32;
    const int bm = blockIdx.y * 128, bn = blockIdx.x * 128;

    auto issue = [&](int it) {
        const int k0 = it * 32, s = it & 1;
        #pragma unroll
        for (int i = 0; i < 4; ++i) {
            int f = tid + i * 256;
            int r = f >> 3, c4 = (f & 7) * 4;
            cpasync16(sb + (unsigned)(s * PROJ_A_WORDS + r * PSA + c4) * 4,
                      A + (size_t)(bm + r) * DM + k0 + c4);
        }
        #pragma unroll
        for (int i = 0; i < 4; ++i) {
            int f = tid + i * 256;
            int r2 = f >> 5, c2 = (f & 31) * 4;
            cpasync16(sb + (unsigned)(2 * PROJ_A_WORDS + s * PROJ_B_WORDS + r2 * PSB + c2) * 4,
                      W + (size_t)(k0 + r2) * DM + bn + c2);
        }
    };

    float acc[4][4][4] = {};

    issue(0); cp_commit();
    for (int it = 0; it < 32; ++it) {
        __syncthreads();                 // prior readers of buf[(it+1)&1] done
        if (it + 1 < 32) { issue(it + 1); cp_commit(); }
        cp_wait(it + 1 < 32);
        __syncthreads();
        const unsigned* As = (const unsigned*)(psm + (it & 1) * PROJ_A_WORDS);
        const unsigned* Bs = (const unsigned*)(psm + 2 * PROJ_A_WORDS + (it & 1) * PROJ_B_WORDS);

        #pragma unroll
        for (int kk = 0; kk < 4; ++kk) {
            unsigned afr[4][4], bfr[4][2];
            #pragma unroll
            for (int mi = 0; mi < 4; ++mi) {
                int r = wm + mi * 16 + (lane >> 2);
                int c = kk * 8 + (lane & 3);
                afr[mi][0] = As[r * PSA + c];
                afr[mi][1] = As[(r + 8) * PSA + c];
                afr[mi][2] = As[r * PSA + c + 4];
                afr[mi][3] = As[(r + 8) * PSA + c + 4];
            }
            #pragma unroll
            for (int ni = 0; ni < 4; ++ni) {
                int n = wn + ni * 8 + (lane >> 2);
                int c = kk * 8 + (lane & 3);
                bfr[ni][0] = Bs[c * PSB + n];
                bfr[ni][1] = Bs[(c + 4) * PSB + n];
            }
            #pragma unroll
            for (int mi = 0; mi < 4; ++mi)
                #pragma unroll
                for (int ni = 0; ni < 4; ++ni)
                    mma8(acc[mi][ni], afr[mi], bfr[ni]);
        }
    }

    #pragma unroll
    for (int mi = 0; mi < 4; ++mi)
        #pragma unroll
        for (int ni = 0; ni < 4; ++ni)
            #pragma unroll
            for (int e = 0; e < 4; ++e) {
                int m = bm + wm + mi * 16 + (lane >> 2) + ((e >= 2) ? 8 : 0);
                int n = bn + wn + ni * 8 + (lane & 3) * 2 + (e & 1);
                float v = acc[mi][ni][e] + bias[n];
                if (EPI == 0) {
                    int b = m >> 11, s = m & (S_ - 1);
                    int h = n >> 6, d = n & (DK - 1);
                    C[(((size_t)b * NH + h) * S_ + s) * DK + d] = v;
                } else {
                    C[(size_t)m * DM + n] = v;
                }
            }
}

// ---------------------------------------------------------------------------
// Fused attention, 512 threads.
// Qs: tf32(rna) permuted (stride 72). Pass 1 holds Q fragments in REGISTERS
// (tile-invariant -> loaded once). K/V raw f32 cp.async double-buffered.
// Pass 2: shuffle-exchange P; AV k-split; cross-warp reduce at end.
// ---------------------------------------------------------------------------
#define QS_STRIDE 72
#define KV_STRIDE 68
#define OFF_Q   0
#define Q_BYTES (128 * QS_STRIDE * 4)                 // 36,864
#define KB_BYTES (128 * KV_STRIDE * 4)                // 34,816
#define OFF_K   (OFF_Q + Q_BYTES)                     // 36,864
#define OFF_V   (OFF_K + 2 * KB_BYTES)                // 106,496
#define OFF_SM  (OFF_V + 2 * KB_BYTES)                // 176,128
#define OFF_SS  (OFF_SM + 512)                        // 176,640
#define FUSED_SMEM (OFF_SS + 512)                     // 177,152

__global__ void __launch_bounds__(512, 1)
fused_attn(const float* __restrict__ Q, const float* __restrict__ Km,
           const float* __restrict__ V, float* __restrict__ attn,
           float* __restrict__ ctx)
{
    extern __shared__ unsigned char smem_raw[];
    unsigned* Qs = (unsigned*)(smem_raw + OFF_Q);
    float* sM    = (float*)(smem_raw + OFF_SM);
    float* sSinv = (float*)(smem_raw + OFF_SS);
    // inter-pass reduction scratch lives in the (then-idle) V buffers
    float* rowm  = (float*)(smem_raw + OFF_V);
    float* rowss = rowm + 128 * 4;

    const unsigned sb = (unsigned)__cvta_generic_to_shared(smem_raw);
    const int tid = threadIdx.x;
    const int lane = tid & 31, wid = tid >> 5;
    const int wm = (wid & 3) * 32;          // warp q-rows
    const int wn = (wid >> 2) * 32;         // warp score cols (and AV k-range)
    const int q0 = blockIdx.x * 128;
    const int bh = blockIdx.y;
    const float scale = 0.125f;

    const float* Qb = Q + (size_t)bh * S_ * DK;
    const float* Kb = Km + (size_t)bh * S_ * DK;
    const float* Vb = V + (size_t)bh * S_ * DK;

    // Load Q tile (128 x 64), rna-tf32, permuted layout for LDS.64 a-frags
    #pragma unroll
    for (int i = 0; i < 4; ++i) {
        int f = tid + i * 512;
        int r = f >> 4, c = (f & 15) * 4;
        float4 v = *reinterpret_cast<const float4*>(Qb + (size_t)(q0 + r) * DK + c);
        int base = r * QS_STRIDE + ((c >> 3) << 3) + ((c >> 2) & 1);
        Qs[base]     = f2tf(v.x);
        Qs[base + 2] = f2tf(v.y);
        Qs[base + 4] = f2tf(v.z);
        Qs[base + 6] = f2tf(v.w);
    }

    auto issueK = [&](int t) {
        #pragma unroll
        for (int i = 0; i < 4; ++i) {
            int f = tid + i * 512;
            int r = f >> 4, c4 = (f & 15) * 4;
            unsigned dst = sb + OFF_K + (t & 1) * KB_BYTES + (r * KV_STRIDE + c4) * 4;
            cpasync16(dst, Kb + (size_t)(t * 128 + r) * DK + c4);
        }
    };
    auto issueV = [&](int t) {
        #pragma unroll
        for (int i = 0; i < 4; ++i) {
            int f = tid + i * 512;
            int r = f >> 4, c4 = (f & 15) * 4;
            unsigned dst = sb + OFF_V + (t & 1) * KB_BYTES + (r * KV_STRIDE + c4) * 4;
            cpasync16(dst, Vb + (size_t)(t * 128 + r) * DK + c4);
        }
    };

    float mreg[2][2], sreg[2][2];
    #pragma unroll
    for (int mi = 0; mi < 2; ++mi)
        #pragma unroll
        for (int e = 0; e < 2; ++e) { mreg[mi][e] = -INFINITY; sreg[mi][e] = 0.f; }

    // ---------------- Pass 1: row max + sum (Q frags in registers) --------
    issueK(0); cp_commit();
    __syncthreads();                 // Q staging visible to all
    unsigned qfr[8][2][4];
    #pragma unroll
    for (int kk = 0; kk < 8; ++kk) {
        const int cbq = kk * 8 + 2 * (lane & 3);
        #pragma unroll
        for (int mi = 0; mi < 2; ++mi) {
            int r = wm + mi * 16 + (lane >> 2);
            uint2 u0 = *reinterpret_cast<const uint2*>(&Qs[r * QS_STRIDE + cbq]);
            uint2 u1 = *reinterpret_cast<const uint2*>(&Qs[(r + 8) * QS_STRIDE + cbq]);
            qfr[kk][mi][0] = u0.x; qfr[kk][mi][1] = u1.x;
            qfr[kk][mi][2] = u0.y; qfr[kk][mi][3] = u1.y;
        }
    }

    for (int t = 0; t < S_ / 128; ++t) {
        __syncthreads();                         // prior readers of buf[(t+1)&1] done
        if (t + 1 < S_ / 128) { issueK(t + 1); cp_commit(); }
        cp_wait(t + 1 < S_ / 128);
        __syncthreads();
        const unsigned* Kc = (const unsigned*)(smem_raw + OFF_K + (t & 1) * KB_BYTES);

        float sacc[2][4][4] = {};
        #pragma unroll
        for (int kk = 0; kk < 8; ++kk) {
            unsigned bfr[4][2];
            const int c = kk * 8 + (lane & 3);
            #pragma unroll
            for (int ni = 0; ni < 4; ++ni) {
                int n = wn + ni * 8 + (lane >> 2);
                bfr[ni][0] = Kc[n * KV_STRIDE + c];
                bfr[ni][1] = Kc[n * KV_STRIDE + c + 4];
            }
            #pragma unroll
            for (int mi = 0; mi < 2; ++mi)
                #pragma unroll
                for (int ni = 0; ni < 4; ++ni)
                    mma8(sacc[mi][ni], qfr[kk][mi], bfr[ni]);
        }

        #pragma unroll
        for (int mi = 0; mi < 2; ++mi)
            #pragma unroll
            for (int e = 0; e < 2; ++e) {
                float lm = -INFINITY;
                #pragma unroll
                for (int ni = 0; ni < 4; ++ni)
                    lm = fmaxf(lm, fmaxf(sacc[mi][ni][e * 2], sacc[mi][ni][e * 2 + 1]));
                lm *= scale;
                float nm = fmaxf(mreg[mi][e], lm);
                float add = 0.f;
                #pragma unroll
                for (int ni = 0; ni < 4; ++ni) {
                    add += __expf(sacc[mi][ni][e * 2] * scale - nm);
                    add += __expf(sacc[mi][ni][e * 2 + 1] * scale - nm);
                }
                sreg[mi][e] = sreg[mi][e] * __expf(mreg[mi][e] - nm) + add;
                mreg[mi][e] = nm;
            }
    }

    // ---------------- Cross-lane / cross-warp reduction ----------------
    #pragma unroll
    for (int mi = 0; mi < 2; ++mi)
        #pragma unroll
        for (int e = 0; e < 2; ++e) {
            float m = mreg[mi][e], s = sreg[mi][e];
            #pragma unroll
            for (int off = 1; off <= 2; off <<= 1) {
                float om = __shfl_xor_sync(0xFFFFFFFFu, m, off);
                float os = __shfl_xor_sync(0xFFFFFFFFu, s, off);
                float nm = fmaxf(m, om);
                s = s * __expf(m - nm) + os * __expf(om - nm);
                m = nm;
            }
            mreg[mi][e] = m; sreg[mi][e] = s;
        }
    __syncthreads();
    if ((lane & 3) == 0) {
        int g = wid >> 2;
        #pragma unroll
        for (int mi = 0; mi < 2; ++mi)
            #pragma unroll
            for (int e = 0; e < 2; ++e) {
                int r = wm + mi * 16 + (lane >> 2) + e * 8;
                rowm[r * 4 + g] = mreg[mi][e];
                rowss[r * 4 + g] = sreg[mi][e];
            }
    }
    __syncthreads();
    if (tid < 128) {
        float M = -INFINITY;
        #pragma unroll
        for (int g = 0; g < 4; ++g) M = fmaxf(M, rowm[tid * 4 + g]);
        float S = 0.f;
        #pragma unroll
        for (int g = 0; g < 4; ++g) S += rowss[tid * 4 + g] * __expf(rowm[tid * 4 + g] - M);
        sM[tid] = M;
        sSinv[tid] = 1.0f / S;
    }
    __syncthreads();

    float Mf[2][2], Sf[2][2];
    #pragma unroll
    for (int mi = 0; mi < 2; ++mi)
        #pragma unroll
        for (int e = 0; e < 2; ++e) {
            int r = wm + mi * 16 + (lane >> 2) + e * 8;
            Mf[mi][e] = sM[r];
            Sf[mi][e] = sSinv[r];
        }

    // ---------------- Pass 2: recompute, write attn, partial P@V ----------
    float acco[2][8][4] = {};     // rows: warp's 32 q-rows; cols: full d=64
    float* attn_b = attn + (size_t)bh * S_ * S_;
    const int b = bh >> 4, h = bh & (NH - 1);
    const unsigned FULL = 0xFFFFFFFFu;
    const int src1 = (lane & ~3) | ((lane & 3) >> 1);
    const int src2 = src1 + 2;
    const bool sel_hi = (lane & 1);

    __syncthreads();              // rowm/rowss reads done before V cp.async overwrites
    issueK(0); issueV(0); cp_commit();
    for (int t = 0; t < S_ / 128; ++t) {
        __syncthreads();
        if (t + 1 < S_ / 128) { issueK(t + 1); issueV(t + 1); cp_commit(); }
        cp_wait(t + 1 < S_ / 128);
        __syncthreads();
        const unsigned* Kc = (const unsigned*)(smem_raw + OFF_K + (t & 1) * KB_BYTES);
        const unsigned* Vc = (const unsigned*)(smem_raw + OFF_V + (t & 1) * KB_BYTES);

        float sacc[2][4][4] = {};
        #pragma unroll
        for (int kk = 0; kk < 8; ++kk) {
            unsigned afr[2][4], bfr[4][2];
            const int cbq = kk * 8 + 2 * (lane & 3);
            #pragma unroll
            for (int mi = 0; mi < 2; ++mi) {
                int r = wm + mi * 16 + (lane >> 2);
                uint2 u0 = *reinterpret_cast<const uint2*>(&Qs[r * QS_STRIDE + cbq]);
                uint2 u1 = *reinterpret_cast<const uint2*>(&Qs[(r + 8) * QS_STRIDE + cbq]);
                afr[mi][0] = u0.x; afr[mi][1] = u1.x; afr[mi][2] = u0.y; afr[mi][3] = u1.y;
            }
            const int c = kk * 8 + (lane & 3);
            #pragma unroll
            for (int ni = 0; ni < 4; ++ni) {
                int n = wn + ni * 8 + (lane >> 2);
                bfr[ni][0] = Kc[n * KV_STRIDE + c];
                bfr[ni][1] = Kc[n * KV_STRIDE + c + 4];
            }
            #pragma unroll
            for (int mi = 0; mi < 2; ++mi)
                #pragma unroll
                for (int ni = 0; ni < 4; ++ni)
                    mma8(sacc[mi][ni], afr[mi], bfr[ni]);
        }

        // per ni (== AV kk'): P, attn write, shuffle-exchange, AV MMA
        #pragma unroll
        for (int ni = 0; ni < 4; ++ni) {
            unsigned afr2[2][4];
            #pragma unroll
            for (int mi = 0; mi < 2; ++mi) {
                int r0 = wm + mi * 16 + (lane >> 2);
                int c0 = wn + ni * 8 + 2 * (lane & 3);
                float p0 = __expf(sacc[mi][ni][0] * scale - Mf[mi][0]) * Sf[mi][0];
                float p1 = __expf(sacc[mi][ni][1] * scale - Mf[mi][0]) * Sf[mi][0];
                float p2 = __expf(sacc[mi][ni][2] * scale - Mf[mi][1]) * Sf[mi][1];
                float p3 = __expf(sacc[mi][ni][3] * scale - Mf[mi][1]) * Sf[mi][1];
                *reinterpret_cast<float2*>(attn_b + (size_t)(q0 + r0) * S_ + t * 128 + c0) =
                    make_float2(p0, p1);
                *reinterpret_cast<float2*>(attn_b + (size_t)(q0 + r0 + 8) * S_ + t * 128 + c0) =
                    make_float2(p2, p3);
                unsigned u0 = f2tf(p0), u1 = f2tf(p1), u2 = f2tf(p2), u3 = f2tf(p3);
                // acc layout -> A-frag layout (16x8 block), pure lane permutation
                unsigned t00 = __shfl_sync(FULL, u0, src1);
                unsigned t01 = __shfl_sync(FULL, u1, src1);
                unsigned t10 = __shfl_sync(FULL, u2, src1);
                unsigned t11 = __shfl_sync(FULL, u3, src1);
                unsigned t20 = __shfl_sync(FULL, u0, src2);
                unsigned t21 = __shfl_sync(FULL, u1, src2);
                unsigned t30 = __shfl_sync(FULL, u2, src2);
                unsigned t31 = __shfl_sync(FULL, u3, src2);
                afr2[mi][0] = sel_hi ? t01 : t00;
                afr2[mi][1] = sel_hi ? t11 : t10;
                afr2[mi][2] = sel_hi ? t21 : t20;
                afr2[mi][3] = sel_hi ? t31 : t30;
            }
            const int cb = wn + ni * 8;       // this warp's 8 V seq-rows
            #pragma unroll
            for (int ni2 = 0; ni2 < 8; ++ni2) {
                unsigned bfr[2];
                bfr[0] = Vc[(cb + (lane & 3)) * KV_STRIDE + ni2 * 8 + (lane >> 2)];
                bfr[1] = Vc[(cb + (lane & 3) + 4) * KV_STRIDE + ni2 * 8 + (lane >> 2)];
                mma8(acco[0][ni2], afr2[0], bfr);
                mma8(acco[1][ni2], afr2[1], bfr);
            }
        }
    }

    // ---------------- Cross-warp acco reduction (k-split x4) --------------
    __syncthreads();
    float* red = (float*)(smem_raw + OFF_K);   // 512*64*4 = 131072 fits K+V bufs
    {
        int base = tid * 64;
        #pragma unroll
        for (int mi = 0; mi < 2; ++mi)
            #pragma unroll
            for (int ni2 = 0; ni2 < 8; ++ni2)
                #pragma unroll
                for (int e = 0; e < 4; ++e)
                    red[base + mi * 32 + ni2 * 4 + e] = acco[mi][ni2][e];
    }
    __syncthreads();
    {
        const int wmg = wid & 3, gg = wid >> 2;
        #pragma unroll
        for (int nn = 0; nn < 2; ++nn) {
            int ni2 = gg * 2 + nn;
            #pragma unroll
            for (int mi = 0; mi < 2; ++mi)
                #pragma unroll
                for (int e = 0; e < 4; ++e) {
                    float s = 0.f;
                    #pragma unroll
                    for (int g = 0; g < 4; ++g)
                        s += red[((4 * g + wmg) * 32 + lane) * 64 + mi * 32 + ni2 * 4 + e];
                    int row = q0 + wmg * 32 + mi * 16 + (lane >> 2) + ((e >= 2) ? 8 : 0);
                    int d = ni2 * 8 + (lane & 3) * 2 + (e & 1);
                    ctx[((size_t)b * S_ + row) * DM + h * DK + d] = s;
                }
        }
    }
}

// ---------------------------------------------------------------------------
extern "C" void kernel_launch(void* const* d_in, const int* in_sizes, int n_in,
                              void* d_out, int out_size)
{
    const float* query = (const float*)d_in[0];
    const float* key   = (const float*)d_in[1];
    const float* value = (const float*)d_in[2];
    const float* w_q = (const float*)d_in[3];
    const float* b_q = (const float*)d_in[4];
    const float* w_k = (const float*)d_in[5];
    const float* b_k = (const float*)d_in[6];
    const float* w_v = (const float*)d_in[7];
    const float* b_v = (const float*)d_in[8];
    const float* w_o = (const float*)d_in[9];
    const float* b_o = (const float*)d_in[10];

    float* out = (float*)d_out;
    float* attn = out + OUT_ELEMS;   // (output, attn) concatenated

    float* Qp; cudaGetSymbolAddress((void**)&Qp, g_Q);
    float* Kp; cudaGetSymbolAddress((void**)&Kp, g_K);
    float* Vp; cudaGetSymbolAddress((void**)&Vp, g_V);
    float* Cp; cudaGetSymbolAddress((void**)&Cp, g_ctx);

    cudaFuncSetAttribute(fused_attn, cudaFuncAttributeMaxDynamicSharedMemorySize,
                         FUSED_SMEM);
    cudaFuncSetAttribute(gemm_proj<0>, cudaFuncAttributeMaxDynamicSharedMemorySize,
                         PROJ_SMEM);
    cudaFuncSetAttribute(gemm_proj<1>, cudaFuncAttributeMaxDynamicSharedMemorySize,
                         PROJ_SMEM);

    dim3 gproj(DM / 128, (B_ * S_) / 128, 1);   // (8, 64)
    gemm_proj<0><<<gproj, 256, PROJ_SMEM>>>(query, w_q, Qp, b_q);
    gemm_proj<0><<<gproj, 256, PROJ_SMEM>>>(key,   w_k, Kp, b_k);
    gemm_proj<0><<<gproj, 256, PROJ_SMEM>>>(value, w_v, Vp, b_v);

    fused_attn<<<dim3(S_ / 128, B_ * NH), 512, FUSED_SMEM>>>(Qp, Kp, Vp, attn, Cp);

    gemm_proj<1><<<gproj, 256, PROJ_SMEM>>>(Cp, w_o, out, b_o);
}